// round 12
// baseline (speedup 1.0000x reference)
#include <cuda_runtime.h>
#include <math.h>

#define NMAX     8192
#define NCMAX    4096          // max cells (16^3)
#define CAP      16            // bucket capacity per cell (lambda ~3.1)
#define NBLK     128
#define NTHR     1024
#define NWARP    (NTHR / 32)   // 32 warps/block -> 4096 warps
#define NWTOT    (NBLK * NWARP)
#define CPB      (NCMAX / NBLK)  // cells zeroed per block
#define LIST_CAP 160           // per-warp compacted candidate list
#define CUTOFF   1.5f

// Deterministic-structure scratch (no device-side allocation allowed).
__device__ float4   g_bucket[NCMAX * CAP];  // (fx,fy,fz, bits(idx<<3|species))
__device__ int      g_count[2][NCMAX];      // double-buffered cell counts
__device__ float    g_ecell[NCMAX];         // per-cell energies
__device__ unsigned g_tick;                 // epoch ticket (monotonic)
__device__ unsigned g_barc;                 // grid-barrier ticket (monotonic)
__device__ unsigned g_done;                 // completion ticket (monotonic)

// Grid barrier: 128 blocks x 1 block/SM <= 148 SMs -> co-resident, no deadlock.
// Monotonic ticket => graph-replay-safe. release-add / acquire-poll gives the
// happens-before chain; bar.sync (morally strong) extends it block-wide.
__device__ __forceinline__ void grid_bar()
{
    __syncthreads();
    if (threadIdx.x == 0) {
        unsigned ticket;
        asm volatile("atom.release.gpu.global.add.u32 %0, [%1], %2;"
                     : "=r"(ticket) : "l"(&g_barc), "r"(1u) : "memory");
        unsigned target = (ticket / NBLK + 1u) * NBLK;
        unsigned cur;
        do {
            asm volatile("ld.acquire.gpu.global.u32 %0, [%1];"
                         : "=r"(cur) : "l"(&g_barc) : "memory");
            if (cur >= target) break;
            __nanosleep(32);
        } while (true);
    }
    __syncthreads();
}

__global__ __launch_bounds__(NTHR)
void fused_kernel(const float* __restrict__ pos,
                  const float* __restrict__ cell,
                  const float* __restrict__ sigm,
                  const float* __restrict__ epsm,
                  const float* __restrict__ alpm,
                  const int*   __restrict__ species,
                  float* __restrict__ out, int n)
{
    __shared__ float4   s_tab[64];            // {1/sig, alpha-1, eps/al, eps/sig}
    __shared__ float    s_inv[9], s_cm[9];
    __shared__ int      s_dims[4];            // ncx, ncy, ncz, ncell
    __shared__ unsigned s_epoch;
    __shared__ int      s_list[NWARP * LIST_CAP];   // compacted candidates
    __shared__ float    s_red[NTHR];
    __shared__ int      s_last;

    const int tid  = threadIdx.x;
    const int lane = tid & 31;
    const int warp = tid >> 5;

    // ---- prologue: epoch ticket, species tables, geometry ------------------
    if (tid < 64) {
        float sg = sigm[tid], ep = epsm[tid], al = alpm[tid];
        s_tab[tid] = make_float4(1.0f / sg, al - 1.0f, ep / al, ep / sg);
    }
    if (tid == 0) {
        unsigned t;
        asm volatile("atom.relaxed.gpu.global.add.u32 %0, [%1], %2;"
                     : "=r"(t) : "l"(&g_tick), "r"(1u) : "memory");
        s_epoch = t / NBLK;          // same value for every block of a launch

        float c00=cell[0], c01=cell[1], c02=cell[2];
        float c10=cell[3], c11=cell[4], c12=cell[5];
        float c20=cell[6], c21=cell[7], c22=cell[8];
        float cof00 =  (c11*c22 - c12*c21);
        float cof01 = -(c10*c22 - c12*c20);
        float cof02 =  (c10*c21 - c11*c20);
        float cof10 = -(c01*c22 - c02*c21);
        float cof11 =  (c00*c22 - c02*c20);
        float cof12 = -(c00*c21 - c01*c20);
        float cof20 =  (c01*c12 - c02*c11);
        float cof21 = -(c00*c12 - c02*c10);
        float cof22 =  (c00*c11 - c01*c10);
        float det = c00*cof00 + c01*cof01 + c02*cof02;
        float id  = 1.0f / det;
        s_inv[0]=cof00*id; s_inv[1]=cof10*id; s_inv[2]=cof20*id;
        s_inv[3]=cof01*id; s_inv[4]=cof11*id; s_inv[5]=cof21*id;
        s_inv[6]=cof02*id; s_inv[7]=cof12*id; s_inv[8]=cof22*id;
        s_cm[0]=c00; s_cm[1]=c01; s_cm[2]=c02;
        s_cm[3]=c10; s_cm[4]=c11; s_cm[5]=c12;
        s_cm[6]=c20; s_cm[7]=c21; s_cm[8]=c22;
        float lx = sqrtf(c00*c00 + c01*c01 + c02*c02);
        float ly = sqrtf(c10*c10 + c11*c11 + c12*c12);
        float lz = sqrtf(c20*c20 + c21*c21 + c22*c22);
        int ncx = max(1, min(16, (int)floorf(lx / CUTOFF)));
        int ncy = max(1, min(16, (int)floorf(ly / CUTOFF)));
        int ncz = max(1, min(16, (int)floorf(lz / CUTOFF)));
        s_dims[0] = ncx; s_dims[1] = ncy; s_dims[2] = ncz;
        s_dims[3] = ncx * ncy * ncz;
    }
    __syncthreads();

    const int buf = (int)(s_epoch & 1u);
    const int ncx = s_dims[0], ncy = s_dims[1], ncz = s_dims[2];
    const int ncell = s_dims[3];
    const int apb = (n + NBLK - 1) / NBLK;     // atoms per block (=32 @ n=4096)

    // ---- P1: balanced per-block bin + zero (minimal barrier skew) ----------
    {
        int i0 = blockIdx.x * apb;
        int i1 = min(i0 + apb, n);
        for (int i = i0 + tid; i < i1; i += NTHR) {   // tid<apb only
            float px = pos[3*i], py = pos[3*i+1], pz = pos[3*i+2];
            float fx = px*s_inv[0] + py*s_inv[3] + pz*s_inv[6];
            float fy = px*s_inv[1] + py*s_inv[4] + pz*s_inv[7];
            float fz = px*s_inv[2] + py*s_inv[5] + pz*s_inv[8];
            fx -= floorf(fx); if (fx >= 1.0f) fx = 0.0f;
            fy -= floorf(fy); if (fy >= 1.0f) fy = 0.0f;
            fz -= floorf(fz); if (fz >= 1.0f) fz = 0.0f;
            int cx = min(ncx-1, (int)(fx * (float)ncx));
            int cy = min(ncy-1, (int)(fy * (float)ncy));
            int cz = min(ncz-1, (int)(fz * (float)ncz));
            int cid = (cz * ncy + cy) * ncx + cx;
            float wbits = __int_as_float((i << 3) | (species[i] & 7));
            int slot = atomicAdd(&g_count[buf][cid], 1);
            if (slot < CAP) g_bucket[cid * CAP + slot] = make_float4(fx, fy, fz, wbits);
        }
        int zc = blockIdx.x * CPB + (tid - 32);        // warp 1 zeroes next buf
        if (tid >= 32 && tid < 32 + CPB && zc < NCMAX)
            g_count[buf ^ 1][zc] = 0;
    }

    grid_bar();

    // ---- P2: pairs — ONE WARP PER CELL (stencil/list amortized) ------------
    {
        const float cm0 = s_cm[0], cm1 = s_cm[1], cm2 = s_cm[2];
        const float cm3 = s_cm[3], cm4 = s_cm[4], cm5 = s_cm[5];
        const float cm6 = s_cm[6], cm7 = s_cm[7], cm8 = s_cm[8];
        const int wbase = warp * LIST_CAP;

        for (int c = blockIdx.x * NWARP + warp; c < ncell; c += NWTOT) {
            int cnt_home = g_count[buf][c];
            if (cnt_home == 0) {
                if (lane == 0) g_ecell[c] = 0.0f;
                continue;
            }
            if (cnt_home > CAP) cnt_home = CAP;

            int cx = c % ncx;
            int tq = c / ncx;
            int cy = tq % ncy;
            int cz = tq / ncy;

            int ncid = -1;
            if (lane < 27) {
                int ax = cx + (lane % 3) - 1;
                int ay = cy + ((lane / 3) % 3) - 1;
                int az = cz + (lane / 9) - 1;
                ax += (ax < 0) ? ncx : 0;  ax -= (ax >= ncx) ? ncx : 0;
                ay += (ay < 0) ? ncy : 0;  ay -= (ay >= ncy) ? ncy : 0;
                az += (az < 0) ? ncz : 0;  az -= (az >= ncz) ? ncz : 0;
                ncid = (az * ncy + ay) * ncx + ax;
            }
            unsigned grp = __match_any_sync(0xFFFFFFFFu, ncid);
            bool keep = (lane < 27) && ((__ffs(grp) - 1) == lane);

            int cnt = 0, base = 0;
            if (keep) {
                cnt  = min(g_count[buf][ncid], CAP);
                base = ncid * CAP;
            }

            // warp exclusive scan of cnt -> compacted candidate list (once/cell)
            int incl = cnt;
            #pragma unroll
            for (int off = 1; off < 32; off <<= 1) {
                int v = __shfl_up_sync(0xFFFFFFFFu, incl, off);
                if (lane >= off) incl += v;
            }
            int total = __shfl_sync(0xFFFFFFFFu, incl, 31);
            int offs  = incl - cnt;
            for (int k = 0; k < cnt; k++) {
                int p = offs + k;
                if (p < LIST_CAP) s_list[wbase + p] = base + k;
            }
            if (total > LIST_CAP) total = LIST_CAP;
            __syncwarp();

            float ecell = 0.0f;
            for (int a = 0; a < cnt_home; a++) {
                float4 me = g_bucket[c * CAP + a];   // broadcast load
                int mybits  = __float_as_int(me.w);
                int myspec8 = (mybits & 7) << 3;

                float fxa = 0.f, fya = 0.f, fza = 0.f, en = 0.f;
                for (int j = lane; j < total; j += 32) {
                    float4 o = g_bucket[s_list[wbase + j]];   // L1-hot after a=0
                    int pv = __float_as_int(o.w);
                    float d0 = o.x - me.x; d0 -= rintf(d0);
                    float d1 = o.y - me.y; d1 -= rintf(d1);
                    float d2 = o.z - me.z; d2 -= rintf(d2);
                    float dx = d0*cm0 + d1*cm3 + d2*cm6;
                    float dy = d0*cm1 + d1*cm4 + d2*cm7;
                    float dz = d0*cm2 + d1*cm5 + d2*cm8;
                    float r2   = dx*dx + dy*dy + dz*dz;
                    float rinv = rsqrtf(r2);
                    float r    = r2 * rinv;               // NaN if r2==0 -> masked
                    float4 tb  = s_tab[myspec8 + (pv & 7)];
                    // sigma_max < cutoff: fc>0 implies r<cutoff. fmaxf kills NaN.
                    float fc = fmaxf(1.0f - r * tb.x, 0.0f);
                    fc = (pv == mybits) ? 0.0f : fc;      // mask self
                    float fa1 = __powf(fc, tb.y);         // f^(alpha-1); 0^y = 0
                    en = fmaf(tb.z * fa1, fc, en);        // (eps/al) f^alpha
                    float cf = (fc > 0.0f) ? -tb.w * fa1 * rinv : 0.0f;
                    fxa = fmaf(cf, dx, fxa);
                    fya = fmaf(cf, dy, fya);
                    fza = fmaf(cf, dz, fza);
                }

                #pragma unroll
                for (int off = 16; off; off >>= 1) {      // fixed-order warp tree
                    fxa += __shfl_xor_sync(0xFFFFFFFFu, fxa, off);
                    fya += __shfl_xor_sync(0xFFFFFFFFu, fya, off);
                    fza += __shfl_xor_sync(0xFFFFFFFFu, fza, off);
                    en  += __shfl_xor_sync(0xFFFFFFFFu, en,  off);
                }
                if (lane == 0) {
                    int orig = mybits >> 3;
                    out[1 + 3*orig + 0] = fxa;
                    out[1 + 3*orig + 1] = fya;
                    out[1 + 3*orig + 2] = fza;
                    ecell += en;
                }
            }
            if (lane == 0) g_ecell[c] = ecell;
        }
    }

    // ---- P3: last-arriving block reduces energy ----------------------------
    __syncthreads();
    if (tid == 0) {
        unsigned t2;
        asm volatile("atom.acq_rel.gpu.global.add.u32 %0, [%1], %2;"
                     : "=r"(t2) : "l"(&g_done), "r"(1u) : "memory");
        s_last = ((t2 % NBLK) == NBLK - 1) ? 1 : 0;    // monotonic: replay-safe
    }
    __syncthreads();
    if (s_last) {
        float e = 0.f;
        for (int k = tid; k < ncell; k += NTHR)        // fixed traversal order
            e += __ldcg(&g_ecell[k]);
        s_red[tid] = e;
        __syncthreads();
        for (int off = NTHR / 2; off; off >>= 1) {
            if (tid < off) s_red[tid] += s_red[tid + off];
            __syncthreads();
        }
        if (tid == 0) out[0] = 0.5f * s_red[0];
    }
}

extern "C" void kernel_launch(void* const* d_in, const int* in_sizes, int n_in,
                              void* d_out, int out_size)
{
    const float* pos     = (const float*)d_in[0];
    const float* cell    = (const float*)d_in[1];
    const float* sigm    = (const float*)d_in[2];
    const float* epsm    = (const float*)d_in[3];
    const float* alpm    = (const float*)d_in[4];
    const int*   species = (const int*)  d_in[5];
    const int n = in_sizes[5];
    float* out = (float*)d_out;

    fused_kernel<<<NBLK, NTHR>>>(pos, cell, sigm, epsm, alpm, species, out, n);
}

// round 13
// speedup vs baseline: 1.5884x; 1.5884x over previous
#include <cuda_runtime.h>
#include <math.h>

#define NMAX     8192
#define NCMAX    4096          // max cells (16^3)
#define CAP      16            // bucket capacity per cell (lambda ~3.1)
#define NBLK     128
#define NTHR     1024
#define NWARP    (NTHR / 32)   // 32 warps/block -> 4096 warps
#define NWTOT    (NBLK * NWARP)
#define CPB      (NCMAX / NBLK)  // cells zeroed per block
#define LIST_CAP 160           // per-warp compacted candidate list
#define CUTOFF   1.5f

// Deterministic-structure scratch (no device-side allocation allowed).
__device__ float4   g_bucket[NCMAX * CAP];  // (fx,fy,fz, bits(idx<<3|species))
__device__ float4   g_pfrac[NMAX];          // per-atom frac coords + packed id
__device__ int      g_count[2][NCMAX];      // double-buffered cell counts
__device__ float    g_ewarp[NMAX];          // per-atom energies
__device__ int      g_buf;                  // parity flag (flipped once/launch)
__device__ unsigned g_barc;                 // barrier ticket (monotonic, 2 events/launch)

__global__ __launch_bounds__(NTHR)
void fused_kernel(const float* __restrict__ pos,
                  const float* __restrict__ cell,
                  const float* __restrict__ sigm,
                  const float* __restrict__ epsm,
                  const float* __restrict__ alpm,
                  const int*   __restrict__ species,
                  float* __restrict__ out, int n)
{
    __shared__ float4 s_tab[64];            // {1/sig, alpha-1, eps/al, eps/sig}
    __shared__ float  s_inv[9], s_cm[9];
    __shared__ int    s_dims[3];
    __shared__ int    s_buf;
    __shared__ int    s_list[NWARP * LIST_CAP];   // compacted candidates
    __shared__ float  s_red[NTHR];
    __shared__ int    s_last;

    const int tid  = threadIdx.x;
    const int lane = tid & 31;
    const int warp = tid >> 5;

    // ---- prologue: species tables, geometry, buffer parity -----------------
    if (tid < 64) {
        float sg = sigm[tid], ep = epsm[tid], al = alpm[tid];
        s_tab[tid] = make_float4(1.0f / sg, al - 1.0f, ep / al, ep / sg);
    }
    if (tid == 0) {
        s_buf = g_buf;               // stable for the whole launch (stream order)

        float c00=cell[0], c01=cell[1], c02=cell[2];
        float c10=cell[3], c11=cell[4], c12=cell[5];
        float c20=cell[6], c21=cell[7], c22=cell[8];
        float cof00 =  (c11*c22 - c12*c21);
        float cof01 = -(c10*c22 - c12*c20);
        float cof02 =  (c10*c21 - c11*c20);
        float cof10 = -(c01*c22 - c02*c21);
        float cof11 =  (c00*c22 - c02*c20);
        float cof12 = -(c00*c21 - c01*c20);
        float cof20 =  (c01*c12 - c02*c11);
        float cof21 = -(c00*c12 - c02*c10);
        float cof22 =  (c00*c11 - c01*c10);
        float det = c00*cof00 + c01*cof01 + c02*cof02;
        float id  = 1.0f / det;
        s_inv[0]=cof00*id; s_inv[1]=cof10*id; s_inv[2]=cof20*id;
        s_inv[3]=cof01*id; s_inv[4]=cof11*id; s_inv[5]=cof21*id;
        s_inv[6]=cof02*id; s_inv[7]=cof12*id; s_inv[8]=cof22*id;
        s_cm[0]=c00; s_cm[1]=c01; s_cm[2]=c02;
        s_cm[3]=c10; s_cm[4]=c11; s_cm[5]=c12;
        s_cm[6]=c20; s_cm[7]=c21; s_cm[8]=c22;
        float lx = sqrtf(c00*c00 + c01*c01 + c02*c02);
        float ly = sqrtf(c10*c10 + c11*c11 + c12*c12);
        float lz = sqrtf(c20*c20 + c21*c21 + c22*c22);
        s_dims[0] = max(1, min(16, (int)floorf(lx / CUTOFF)));
        s_dims[1] = max(1, min(16, (int)floorf(ly / CUTOFF)));
        s_dims[2] = max(1, min(16, (int)floorf(lz / CUTOFF)));
    }
    __syncthreads();

    const int buf = s_buf;
    const int ncx = s_dims[0], ncy = s_dims[1], ncz = s_dims[2];
    const int apb = (n + NBLK - 1) / NBLK;     // atoms per block (=32 @ n=4096)

    // ---- P1: balanced per-block bin (warp 0) + zero next buf (warp 1) ------
    {
        int i0 = blockIdx.x * apb;
        int i1 = min(i0 + apb, n);
        for (int i = i0 + tid; i < i1; i += NTHR) {   // tid<apb only
            float px = pos[3*i], py = pos[3*i+1], pz = pos[3*i+2];
            float fx = px*s_inv[0] + py*s_inv[3] + pz*s_inv[6];
            float fy = px*s_inv[1] + py*s_inv[4] + pz*s_inv[7];
            float fz = px*s_inv[2] + py*s_inv[5] + pz*s_inv[8];
            fx -= floorf(fx); if (fx >= 1.0f) fx = 0.0f;
            fy -= floorf(fy); if (fy >= 1.0f) fy = 0.0f;
            fz -= floorf(fz); if (fz >= 1.0f) fz = 0.0f;
            int cx = min(ncx-1, (int)(fx * (float)ncx));
            int cy = min(ncy-1, (int)(fy * (float)ncy));
            int cz = min(ncz-1, (int)(fz * (float)ncz));
            int cid = (cz * ncy + cy) * ncx + cx;
            float wbits = __int_as_float((i << 3) | (species[i] & 7));
            float4 rec  = make_float4(fx, fy, fz, wbits);
            g_pfrac[i] = rec;
            int slot = atomicAdd(&g_count[buf][cid], 1);
            if (slot < CAP) g_bucket[cid * CAP + slot] = rec;
        }
        int zc = blockIdx.x * CPB + (tid - 32);        // warp 1 zeroes next buf
        if (tid >= 32 && tid < 32 + CPB && zc < NCMAX)
            g_count[buf ^ 1][zc] = 0;
    }

    // ---- grid barrier (event 1): 128 co-resident blocks, monotonic ticket --
    __syncthreads();
    if (tid == 0) {
        unsigned ticket;
        asm volatile("atom.release.gpu.global.add.u32 %0, [%1], %2;"
                     : "=r"(ticket) : "l"(&g_barc), "r"(1u) : "memory");
        unsigned target = (ticket / NBLK + 1u) * NBLK;
        unsigned cur;
        do {
            asm volatile("ld.acquire.gpu.global.u32 %0, [%1];"
                         : "=r"(cur) : "l"(&g_barc) : "memory");
            if (cur >= target) break;
            __nanosleep(32);
        } while (true);
    }
    __syncthreads();

    // ---- P2: pairs — warp per atom, compaction + double-buffered loads -----
    {
        const float cm0 = s_cm[0], cm1 = s_cm[1], cm2 = s_cm[2];
        const float cm3 = s_cm[3], cm4 = s_cm[4], cm5 = s_cm[5];
        const float cm6 = s_cm[6], cm7 = s_cm[7], cm8 = s_cm[8];
        const int wbase = warp * LIST_CAP;

        for (int w = blockIdx.x * NWARP + warp; w < n; w += NWTOT) {
            float4 me = g_pfrac[w];
            int myspec8 = (__float_as_int(me.w) & 7) << 3;
            int cx = min(ncx-1, (int)(me.x * (float)ncx));
            int cy = min(ncy-1, (int)(me.y * (float)ncy));
            int cz = min(ncz-1, (int)(me.z * (float)ncz));

            int ncid = -1;
            if (lane < 27) {
                int ax = cx + (lane % 3) - 1;
                int ay = cy + ((lane / 3) % 3) - 1;
                int az = cz + (lane / 9) - 1;
                ax += (ax < 0) ? ncx : 0;  ax -= (ax >= ncx) ? ncx : 0;
                ay += (ay < 0) ? ncy : 0;  ay -= (ay >= ncy) ? ncy : 0;
                az += (az < 0) ? ncz : 0;  az -= (az >= ncz) ? ncz : 0;
                ncid = (az * ncy + ay) * ncx + ax;
            }
            unsigned grp = __match_any_sync(0xFFFFFFFFu, ncid);
            bool keep = (lane < 27) && ((__ffs(grp) - 1) == lane);

            int cnt = 0, base = 0;
            if (keep) {
                cnt  = min(g_count[buf][ncid], CAP);
                base = ncid * CAP;
            }

            // warp exclusive scan of cnt -> compacted candidate list
            int incl = cnt;
            #pragma unroll
            for (int off = 1; off < 32; off <<= 1) {
                int v = __shfl_up_sync(0xFFFFFFFFu, incl, off);
                if (lane >= off) incl += v;
            }
            int total = __shfl_sync(0xFFFFFFFFu, incl, 31);
            int offs  = incl - cnt;
            for (int k = 0; k < cnt; k++) {
                int p = offs + k;
                if (p < LIST_CAP) s_list[wbase + p] = base + k;
            }
            if (total > LIST_CAP) total = LIST_CAP;
            __syncwarp();

            float fxa = 0.f, fya = 0.f, fza = 0.f, en = 0.f;
            // Software-pipelined: prefetch next record behind current compute.
            float4 o_n = make_float4(0.f, 0.f, 0.f, 0.f);
            if (lane < total) o_n = g_bucket[s_list[wbase + lane]];
            for (int j = lane; j < total; j += 32) {
                float4 o = o_n;
                int j2 = j + 32;
                if (j2 < total) o_n = g_bucket[s_list[wbase + j2]];
                int pv = __float_as_int(o.w);
                float d0 = o.x - me.x; d0 -= rintf(d0);
                float d1 = o.y - me.y; d1 -= rintf(d1);
                float d2 = o.z - me.z; d2 -= rintf(d2);
                float dx = d0*cm0 + d1*cm3 + d2*cm6;
                float dy = d0*cm1 + d1*cm4 + d2*cm7;
                float dz = d0*cm2 + d1*cm5 + d2*cm8;
                float r2   = dx*dx + dy*dy + dz*dz;
                float rinv = rsqrtf(r2);
                float r    = r2 * rinv;                // NaN if r2==0 -> masked
                float4 tb  = s_tab[myspec8 + (pv & 7)];
                // sigma_max < cutoff: fc>0 implies r<cutoff. fmaxf kills NaN.
                float fc = fmaxf(1.0f - r * tb.x, 0.0f);
                fc = ((pv >> 3) == w) ? 0.0f : fc;     // mask self
                float fa1 = __powf(fc, tb.y);          // f^(alpha-1); 0^y = 0
                en = fmaf(tb.z * fa1, fc, en);         // (eps/al) f^alpha
                float cf = (fc > 0.0f) ? -tb.w * fa1 * rinv : 0.0f;
                fxa = fmaf(cf, dx, fxa);
                fya = fmaf(cf, dy, fya);
                fza = fmaf(cf, dz, fza);
            }

            #pragma unroll
            for (int off = 16; off; off >>= 1) {       // fixed-order warp tree
                fxa += __shfl_xor_sync(0xFFFFFFFFu, fxa, off);
                fya += __shfl_xor_sync(0xFFFFFFFFu, fya, off);
                fza += __shfl_xor_sync(0xFFFFFFFFu, fza, off);
                en  += __shfl_xor_sync(0xFFFFFFFFu, en,  off);
            }
            if (lane == 0) {
                out[1 + 3*w + 0] = fxa;
                out[1 + 3*w + 1] = fya;
                out[1 + 3*w + 2] = fza;
                g_ewarp[w] = en;
            }
        }
    }

    // ---- event 2 on the same counter: last block reduces + flips parity ----
    __syncthreads();
    if (tid == 0) {
        unsigned t2;
        asm volatile("atom.acq_rel.gpu.global.add.u32 %0, [%1], %2;"
                     : "=r"(t2) : "l"(&g_barc), "r"(1u) : "memory");
        s_last = ((t2 % NBLK) == NBLK - 1) ? 1 : 0;    // monotonic: replay-safe
    }
    __syncthreads();
    if (s_last) {
        float e = 0.f;
        for (int k = tid; k < n; k += NTHR)            // fixed traversal order
            e += __ldcg(&g_ewarp[k]);
        s_red[tid] = e;
        __syncthreads();
        for (int off = NTHR / 2; off; off >>= 1) {
            if (tid < off) s_red[tid] += s_red[tid + off];
            __syncthreads();
        }
        if (tid == 0) {
            out[0] = 0.5f * s_red[0];
            g_buf  = buf ^ 1;          // parity for the next launch
        }
    }
}

extern "C" void kernel_launch(void* const* d_in, const int* in_sizes, int n_in,
                              void* d_out, int out_size)
{
    const float* pos     = (const float*)d_in[0];
    const float* cell    = (const float*)d_in[1];
    const float* sigm    = (const float*)d_in[2];
    const float* epsm    = (const float*)d_in[3];
    const float* alpm    = (const float*)d_in[4];
    const int*   species = (const int*)  d_in[5];
    const int n = in_sizes[5];
    float* out = (float*)d_out;

    fused_kernel<<<NBLK, NTHR>>>(pos, cell, sigm, epsm, alpm, species, out, n);
}

// round 15
// speedup vs baseline: 1.5918x; 1.0022x over previous
#include <cuda_runtime.h>
#include <math.h>

#define NMAX     8192
#define NCMAX    4096          // max cells (16^3)
#define CAP      16            // bucket capacity per cell (lambda ~3.1)
#define NBLK     128
#define NTHR     1024
#define NWARP    (NTHR / 32)   // 32 warps/block -> 4096 warps
#define NWTOT    (NBLK * NWARP)
#define BINBLK   32
#define BINTHR   128
#define LIST_CAP 160           // per-warp compacted candidate list
#define CUTOFF   1.5f

// Deterministic-structure scratch (no device-side allocation allowed).
__device__ float4   g_bucket[NCMAX * CAP];  // (fx,fy,fz, bits(idx<<3|species))
__device__ float4   g_pfrac[NMAX];          // per-atom frac coords + packed id
__device__ int      g_count[2][NCMAX];      // double-buffered cell counts
__device__ float    g_ewarp[NMAX];          // per-atom energies
__device__ int      g_buf;                  // parity flag (flipped once/launch)
__device__ unsigned g_done;                 // completion ticket (monotonic)

// Shared geometry helper: inverse cell + grid dims (redundant per block, cheap).
__device__ __forceinline__ void compute_geom(const float* cell,
                                             float* inv, int* dims)
{
    float c00=cell[0], c01=cell[1], c02=cell[2];
    float c10=cell[3], c11=cell[4], c12=cell[5];
    float c20=cell[6], c21=cell[7], c22=cell[8];
    float cof00 =  (c11*c22 - c12*c21);
    float cof01 = -(c10*c22 - c12*c20);
    float cof02 =  (c10*c21 - c11*c20);
    float cof10 = -(c01*c22 - c02*c21);
    float cof11 =  (c00*c22 - c02*c20);
    float cof12 = -(c00*c21 - c01*c20);
    float cof20 =  (c01*c12 - c02*c11);
    float cof21 = -(c00*c12 - c02*c10);
    float cof22 =  (c00*c11 - c01*c10);
    float det = c00*cof00 + c01*cof01 + c02*cof02;
    float id  = 1.0f / det;
    inv[0]=cof00*id; inv[1]=cof10*id; inv[2]=cof20*id;
    inv[3]=cof01*id; inv[4]=cof11*id; inv[5]=cof21*id;
    inv[6]=cof02*id; inv[7]=cof12*id; inv[8]=cof22*id;
    float lx = sqrtf(c00*c00 + c01*c01 + c02*c02);
    float ly = sqrtf(c10*c10 + c11*c11 + c12*c12);
    float lz = sqrtf(c20*c20 + c21*c21 + c22*c22);
    dims[0] = max(1, min(16, (int)floorf(lx / CUTOFF)));
    dims[1] = max(1, min(16, (int)floorf(ly / CUTOFF)));
    dims[2] = max(1, min(16, (int)floorf(lz / CUTOFF)));
}

// ===================== Kernel A: parallel bin (1 thread/atom) ===============
__global__ __launch_bounds__(BINTHR)
void bin_kernel(const float* __restrict__ pos,
                const float* __restrict__ cell,
                const int*   __restrict__ species, int n)
{
    __shared__ float s_inv[9];
    __shared__ int   s_dims[3];
    __shared__ int   s_buf;

    const int tid = threadIdx.x;
    const int gid = blockIdx.x * BINTHR + tid;

    if (tid == 0) {
        s_buf = g_buf;
        compute_geom(cell, s_inv, s_dims);
    }
    __syncthreads();

    const int buf = s_buf;
    const int ncx = s_dims[0], ncy = s_dims[1], ncz = s_dims[2];
    const int gstride = BINBLK * BINTHR;       // 4096

    // zero the NEXT launch's count buffer (one cell per thread)
    for (int c = gid; c < NCMAX; c += gstride) g_count[buf ^ 1][c] = 0;

    for (int i = gid; i < n; i += gstride) {
        float px = pos[3*i], py = pos[3*i+1], pz = pos[3*i+2];
        float fx = px*s_inv[0] + py*s_inv[3] + pz*s_inv[6];
        float fy = px*s_inv[1] + py*s_inv[4] + pz*s_inv[7];
        float fz = px*s_inv[2] + py*s_inv[5] + pz*s_inv[8];
        fx -= floorf(fx); if (fx >= 1.0f) fx = 0.0f;
        fy -= floorf(fy); if (fy >= 1.0f) fy = 0.0f;
        fz -= floorf(fz); if (fz >= 1.0f) fz = 0.0f;
        int cx = min(ncx-1, (int)(fx * (float)ncx));
        int cy = min(ncy-1, (int)(fy * (float)ncy));
        int cz = min(ncz-1, (int)(fz * (float)ncz));
        int cid = (cz * ncy + cy) * ncx + cx;
        float wbits = __int_as_float((i << 3) | (species[i] & 7));
        float4 rec  = make_float4(fx, fy, fz, wbits);
        g_pfrac[i] = rec;
        int slot = atomicAdd(&g_count[buf][cid], 1);
        if (slot < CAP) g_bucket[cid * CAP + slot] = rec;
    }
}

// ===================== Kernel B: pairs + forces + energy ====================
__global__ __launch_bounds__(NTHR)
void pairs_kernel(const float* __restrict__ cell,
                  const float* __restrict__ sigm,
                  const float* __restrict__ epsm,
                  const float* __restrict__ alpm,
                  float* __restrict__ out, int n)
{
    __shared__ float4 s_tab[64];            // {1/sig, alpha-1, eps/al, eps/sig}
    __shared__ float  s_cm[9];
    __shared__ int    s_dims[3];
    __shared__ int    s_buf;
    __shared__ int    s_list[NWARP * LIST_CAP];   // compacted candidates
    __shared__ float  s_red[NTHR];
    __shared__ int    s_last;

    const int tid  = threadIdx.x;
    const int lane = tid & 31;
    const int warp = tid >> 5;

    if (tid < 64) {
        float sg = sigm[tid], ep = epsm[tid], al = alpm[tid];
        s_tab[tid] = make_float4(1.0f / sg, al - 1.0f, ep / al, ep / sg);
    }
    if (tid < 9) s_cm[tid] = cell[tid];
    if (tid == 0) {
        s_buf = g_buf;
        float dummy_inv[9];
        compute_geom(cell, dummy_inv, s_dims);
    }
    __syncthreads();

    const int buf = s_buf;
    const int ncx = s_dims[0], ncy = s_dims[1], ncz = s_dims[2];
    const float cm0 = s_cm[0], cm1 = s_cm[1], cm2 = s_cm[2];
    const float cm3 = s_cm[3], cm4 = s_cm[4], cm5 = s_cm[5];
    const float cm6 = s_cm[6], cm7 = s_cm[7], cm8 = s_cm[8];
    const int wbase = warp * LIST_CAP;

    for (int w = blockIdx.x * NWARP + warp; w < n; w += NWTOT) {
        float4 me = g_pfrac[w];                 // L1 fresh (flushed at launch)
        int myspec8 = (__float_as_int(me.w) & 7) << 3;
        int cx = min(ncx-1, (int)(me.x * (float)ncx));
        int cy = min(ncy-1, (int)(me.y * (float)ncy));
        int cz = min(ncz-1, (int)(me.z * (float)ncz));

        int ncid = -1;
        if (lane < 27) {
            int ax = cx + (lane % 3) - 1;
            int ay = cy + ((lane / 3) % 3) - 1;
            int az = cz + (lane / 9) - 1;
            ax += (ax < 0) ? ncx : 0;  ax -= (ax >= ncx) ? ncx : 0;
            ay += (ay < 0) ? ncy : 0;  ay -= (ay >= ncy) ? ncy : 0;
            az += (az < 0) ? ncz : 0;  az -= (az >= ncz) ? ncz : 0;
            ncid = (az * ncy + ay) * ncx + ax;
        }
        unsigned grp = __match_any_sync(0xFFFFFFFFu, ncid);
        bool keep = (lane < 27) && ((__ffs(grp) - 1) == lane);

        int cnt = 0, base = 0;
        if (keep) {
            cnt  = min(g_count[buf][ncid], CAP);
            base = ncid * CAP;
        }

        // warp exclusive scan of cnt -> compacted candidate list
        int incl = cnt;
        #pragma unroll
        for (int off = 1; off < 32; off <<= 1) {
            int v = __shfl_up_sync(0xFFFFFFFFu, incl, off);
            if (lane >= off) incl += v;
        }
        int total = __shfl_sync(0xFFFFFFFFu, incl, 31);
        int offs  = incl - cnt;
        for (int k = 0; k < cnt; k++) {
            int p = offs + k;
            if (p < LIST_CAP) s_list[wbase + p] = base + k;
        }
        if (total > LIST_CAP) total = LIST_CAP;
        __syncwarp();

        float fxa = 0.f, fya = 0.f, fza = 0.f, en = 0.f;
        // Software-pipelined: prefetch next record behind current compute.
        float4 o_n = make_float4(0.f, 0.f, 0.f, 0.f);
        if (lane < total) o_n = g_bucket[s_list[wbase + lane]];
        for (int j = lane; j < total; j += 32) {
            float4 o = o_n;
            int j2 = j + 32;
            if (j2 < total) o_n = g_bucket[s_list[wbase + j2]];
            int pv = __float_as_int(o.w);
            float d0 = o.x - me.x; d0 -= rintf(d0);
            float d1 = o.y - me.y; d1 -= rintf(d1);
            float d2 = o.z - me.z; d2 -= rintf(d2);
            float dx = d0*cm0 + d1*cm3 + d2*cm6;
            float dy = d0*cm1 + d1*cm4 + d2*cm7;
            float dz = d0*cm2 + d1*cm5 + d2*cm8;
            float r2   = dx*dx + dy*dy + dz*dz;
            float rinv = rsqrtf(r2);
            float r    = r2 * rinv;                // NaN if r2==0 -> masked
            float4 tb  = s_tab[myspec8 + (pv & 7)];
            // sigma_max < cutoff: fc>0 implies r<cutoff. fmaxf kills NaN.
            float fc = fmaxf(1.0f - r * tb.x, 0.0f);
            fc = ((pv >> 3) == w) ? 0.0f : fc;     // mask self
            float fa1 = __powf(fc, tb.y);          // f^(alpha-1); 0^y = 0
            en = fmaf(tb.z * fa1, fc, en);         // (eps/al) f^alpha
            float cf = (fc > 0.0f) ? -tb.w * fa1 * rinv : 0.0f;
            fxa = fmaf(cf, dx, fxa);
            fya = fmaf(cf, dy, fya);
            fza = fmaf(cf, dz, fza);
        }

        #pragma unroll
        for (int off = 16; off; off >>= 1) {       // fixed-order warp tree
            fxa += __shfl_xor_sync(0xFFFFFFFFu, fxa, off);
            fya += __shfl_xor_sync(0xFFFFFFFFu, fya, off);
            fza += __shfl_xor_sync(0xFFFFFFFFu, fza, off);
            en  += __shfl_xor_sync(0xFFFFFFFFu, en,  off);
        }
        if (lane == 0) {
            out[1 + 3*w + 0] = fxa;
            out[1 + 3*w + 1] = fya;
            out[1 + 3*w + 2] = fza;
            g_ewarp[w] = en;
        }
    }

    // ---- last-arriving block reduces energy + flips parity -----------------
    __syncthreads();
    if (tid == 0) {
        unsigned t2;
        asm volatile("atom.acq_rel.gpu.global.add.u32 %0, [%1], %2;"
                     : "=r"(t2) : "l"(&g_done), "r"(1u) : "memory");
        s_last = ((t2 % NBLK) == NBLK - 1) ? 1 : 0;    // monotonic: replay-safe
    }
    __syncthreads();
    if (s_last) {
        float e = 0.f;
        for (int k = tid; k < n; k += NTHR)            // fixed traversal order
            e += __ldcg(&g_ewarp[k]);
        s_red[tid] = e;
        __syncthreads();
        for (int off = NTHR / 2; off; off >>= 1) {
            if (tid < off) s_red[tid] += s_red[tid + off];
            __syncthreads();
        }
        if (tid == 0) {
            out[0] = 0.5f * s_red[0];
            g_buf  = buf ^ 1;          // parity for the next launch
        }
    }
}

extern "C" void kernel_launch(void* const* d_in, const int* in_sizes, int n_in,
                              void* d_out, int out_size)
{
    const float* pos     = (const float*)d_in[0];
    const float* cell    = (const float*)d_in[1];
    const float* sigm    = (const float*)d_in[2];
    const float* epsm    = (const float*)d_in[3];
    const float* alpm    = (const float*)d_in[4];
    const int*   species = (const int*)  d_in[5];
    const int n = in_sizes[5];
    float* out = (float*)d_out;

    bin_kernel<<<BINBLK, BINTHR>>>(pos, cell, species, n);
    pairs_kernel<<<NBLK, NTHR>>>(cell, sigm, epsm, alpm, out, n);
}

// round 16
// speedup vs baseline: 1.8108x; 1.1376x over previous
#include <cuda_runtime.h>
#include <math.h>

#define NMAX     8192
#define NCMAX    4096          // max cells (16^3)
#define CAP      16            // bucket capacity per cell (lambda ~3.1)
#define PBLK     256           // pairs: 256 blocks
#define PTHR     512           // pairs: 512 threads = 16 warps
#define PWARP    (PTHR / 32)
#define PWTOT    (PBLK * PWARP)   // 4096 warps: one per atom
#define BINBLK   32
#define BINTHR   128
#define LIST_CAP 160           // per-warp compacted candidate list
#define CUTOFF   1.5f

// Scratch (no device-side allocation allowed).
__device__ float4 g_bucket[NCMAX * CAP];  // (fx,fy,fz, bits(idx<<3|species))
__device__ float4 g_pfrac[NMAX];          // per-atom frac coords + packed id
__device__ int    g_count[2][NCMAX];      // double-buffered cell counts
__device__ int    g_buf;                  // parity flag (flipped once/launch)

// Geometry helper: inverse cell + grid dims (redundant per block, cheap).
__device__ __forceinline__ void compute_geom(const float* cell,
                                             float* inv, int* dims)
{
    float c00=cell[0], c01=cell[1], c02=cell[2];
    float c10=cell[3], c11=cell[4], c12=cell[5];
    float c20=cell[6], c21=cell[7], c22=cell[8];
    float cof00 =  (c11*c22 - c12*c21);
    float cof01 = -(c10*c22 - c12*c20);
    float cof02 =  (c10*c21 - c11*c20);
    float cof10 = -(c01*c22 - c02*c21);
    float cof11 =  (c00*c22 - c02*c20);
    float cof12 = -(c00*c21 - c01*c20);
    float cof20 =  (c01*c12 - c02*c11);
    float cof21 = -(c00*c12 - c02*c10);
    float cof22 =  (c00*c11 - c01*c10);
    float det = c00*cof00 + c01*cof01 + c02*cof02;
    float id  = 1.0f / det;
    inv[0]=cof00*id; inv[1]=cof10*id; inv[2]=cof20*id;
    inv[3]=cof01*id; inv[4]=cof11*id; inv[5]=cof21*id;
    inv[6]=cof02*id; inv[7]=cof12*id; inv[8]=cof22*id;
    float lx = sqrtf(c00*c00 + c01*c01 + c02*c02);
    float ly = sqrtf(c10*c10 + c11*c11 + c12*c12);
    float lz = sqrtf(c20*c20 + c21*c21 + c22*c22);
    dims[0] = max(1, min(16, (int)floorf(lx / CUTOFF)));
    dims[1] = max(1, min(16, (int)floorf(ly / CUTOFF)));
    dims[2] = max(1, min(16, (int)floorf(lz / CUTOFF)));
}

// ===================== Kernel A: parallel bin (1 thread/atom) ===============
__global__ __launch_bounds__(BINTHR)
void bin_kernel(const float* __restrict__ pos,
                const float* __restrict__ cell,
                const int*   __restrict__ species,
                float* __restrict__ out, int n)
{
    __shared__ float s_inv[9];
    __shared__ int   s_dims[3];
    __shared__ int   s_buf;

    const int tid = threadIdx.x;
    const int gid = blockIdx.x * BINTHR + tid;

    if (tid == 0) {
        s_buf = g_buf;
        compute_geom(cell, s_inv, s_dims);
        if (blockIdx.x == 0) out[0] = 0.0f;    // energy accumulator
    }
    __syncthreads();

    const int buf = s_buf;
    const int ncx = s_dims[0], ncy = s_dims[1], ncz = s_dims[2];
    const int gstride = BINBLK * BINTHR;       // 4096

    // zero the NEXT launch's count buffer (one cell per thread)
    for (int c = gid; c < NCMAX; c += gstride) g_count[buf ^ 1][c] = 0;

    for (int i = gid; i < n; i += gstride) {
        float px = pos[3*i], py = pos[3*i+1], pz = pos[3*i+2];
        float fx = px*s_inv[0] + py*s_inv[3] + pz*s_inv[6];
        float fy = px*s_inv[1] + py*s_inv[4] + pz*s_inv[7];
        float fz = px*s_inv[2] + py*s_inv[5] + pz*s_inv[8];
        fx -= floorf(fx); if (fx >= 1.0f) fx = 0.0f;
        fy -= floorf(fy); if (fy >= 1.0f) fy = 0.0f;
        fz -= floorf(fz); if (fz >= 1.0f) fz = 0.0f;
        int cx = min(ncx-1, (int)(fx * (float)ncx));
        int cy = min(ncy-1, (int)(fy * (float)ncy));
        int cz = min(ncz-1, (int)(fz * (float)ncz));
        int cid = (cz * ncy + cy) * ncx + cx;
        float wbits = __int_as_float((i << 3) | (species[i] & 7));
        float4 rec  = make_float4(fx, fy, fz, wbits);
        g_pfrac[i] = rec;
        int slot = atomicAdd(&g_count[buf][cid], 1);
        if (slot < CAP) g_bucket[cid * CAP + slot] = rec;
    }
}

// ===================== Kernel B: pairs + forces + energy ====================
__global__ __launch_bounds__(PTHR)
void pairs_kernel(const float* __restrict__ cell,
                  const float* __restrict__ sigm,
                  const float* __restrict__ epsm,
                  const float* __restrict__ alpm,
                  float* __restrict__ out, int n)
{
    __shared__ float4 s_tab[64];            // {1/sig, alpha-1, eps/al, eps/sig}
    __shared__ float  s_cm[9];
    __shared__ int    s_dims[3];
    __shared__ int    s_buf;
    __shared__ int    s_list[PWARP * LIST_CAP];   // compacted candidates
    __shared__ float  s_eblk[PWARP];

    const int tid  = threadIdx.x;
    const int lane = tid & 31;
    const int warp = tid >> 5;

    if (tid < 64) {
        float sg = sigm[tid], ep = epsm[tid], al = alpm[tid];
        s_tab[tid] = make_float4(1.0f / sg, al - 1.0f, ep / al, ep / sg);
    }
    if (tid < 9) s_cm[tid] = cell[tid];
    if (tid == 0) {
        s_buf = g_buf;
        float dummy_inv[9];
        compute_geom(cell, dummy_inv, s_dims);
    }
    __syncthreads();

    const int buf = s_buf;
    const int ncx = s_dims[0], ncy = s_dims[1], ncz = s_dims[2];
    const float cm0 = s_cm[0], cm1 = s_cm[1], cm2 = s_cm[2];
    const float cm3 = s_cm[3], cm4 = s_cm[4], cm5 = s_cm[5];
    const float cm6 = s_cm[6], cm7 = s_cm[7], cm8 = s_cm[8];
    const int wbase = warp * LIST_CAP;

    float en_warp = 0.0f;

    for (int w = blockIdx.x * PWARP + warp; w < n; w += PWTOT) {
        float4 me = g_pfrac[w];                 // L1 fresh (flushed at launch)
        int mybits  = __float_as_int(me.w);
        int myspec8 = (mybits & 7) << 3;
        int cx = min(ncx-1, (int)(me.x * (float)ncx));
        int cy = min(ncy-1, (int)(me.y * (float)ncy));
        int cz = min(ncz-1, (int)(me.z * (float)ncz));

        int ncid = -1;
        if (lane < 27) {
            int ax = cx + (lane % 3) - 1;
            int ay = cy + ((lane / 3) % 3) - 1;
            int az = cz + (lane / 9) - 1;
            ax += (ax < 0) ? ncx : 0;  ax -= (ax >= ncx) ? ncx : 0;
            ay += (ay < 0) ? ncy : 0;  ay -= (ay >= ncy) ? ncy : 0;
            az += (az < 0) ? ncz : 0;  az -= (az >= ncz) ? ncz : 0;
            ncid = (az * ncy + ay) * ncx + ax;
        }
        unsigned grp = __match_any_sync(0xFFFFFFFFu, ncid);
        bool keep = (lane < 27) && ((__ffs(grp) - 1) == lane);

        int cnt = 0, base = 0;
        if (keep) {
            cnt  = min(g_count[buf][ncid], CAP);
            base = ncid * CAP;
        }

        // warp exclusive scan of cnt -> compacted candidate list
        int incl = cnt;
        #pragma unroll
        for (int off = 1; off < 32; off <<= 1) {
            int v = __shfl_up_sync(0xFFFFFFFFu, incl, off);
            if (lane >= off) incl += v;
        }
        int total = __shfl_sync(0xFFFFFFFFu, incl, 31);
        int offs  = incl - cnt;
        for (int k = 0; k < cnt; k++) {
            int p = offs + k;
            if (p < LIST_CAP) s_list[wbase + p] = base + k;
        }
        if (total > LIST_CAP) total = LIST_CAP;
        __syncwarp();

        float fxa = 0.f, fya = 0.f, fza = 0.f, en = 0.f;
        for (int j = lane; j < total; j += 32) {
            float4 o = g_bucket[s_list[wbase + j]];
            int pv = __float_as_int(o.w);
            float d0 = o.x - me.x; d0 -= rintf(d0);
            float d1 = o.y - me.y; d1 -= rintf(d1);
            float d2 = o.z - me.z; d2 -= rintf(d2);
            float dx = d0*cm0 + d1*cm3 + d2*cm6;
            float dy = d0*cm1 + d1*cm4 + d2*cm7;
            float dz = d0*cm2 + d1*cm5 + d2*cm8;
            float r2   = dx*dx + dy*dy + dz*dz;
            float rinv = rsqrtf(r2);
            float r    = r2 * rinv;                // NaN if r2==0 -> masked
            float4 tb  = s_tab[myspec8 + (pv & 7)];
            // sigma_max < cutoff: fc>0 implies r<cutoff. fmaxf kills NaN.
            float fc = fmaxf(1.0f - r * tb.x, 0.0f);
            fc = (pv == mybits) ? 0.0f : fc;       // mask self (full-bits cmp)
            float fa1 = __powf(fc, tb.y);          // f^(alpha-1); 0^y = 0
            en = fmaf(tb.z * fa1, fc, en);         // (eps/al) f^alpha
            float cf = (fc > 0.0f) ? -tb.w * fa1 * rinv : 0.0f;
            fxa = fmaf(cf, dx, fxa);
            fya = fmaf(cf, dy, fya);
            fza = fmaf(cf, dz, fza);
        }

        #pragma unroll
        for (int off = 16; off; off >>= 1) {       // fixed-order warp tree
            fxa += __shfl_xor_sync(0xFFFFFFFFu, fxa, off);
            fya += __shfl_xor_sync(0xFFFFFFFFu, fya, off);
            fza += __shfl_xor_sync(0xFFFFFFFFu, fza, off);
            en  += __shfl_xor_sync(0xFFFFFFFFu, en,  off);
        }
        if (lane == 0) {
            out[1 + 3*w + 0] = fxa;
            out[1 + 3*w + 1] = fya;
            out[1 + 3*w + 2] = fza;
        }
        en_warp += en;                             // same in all lanes
    }

    // ---- block energy: smem tree + ONE atomicAdd per block -----------------
    if (lane == 0) s_eblk[warp] = en_warp;
    __syncthreads();
    if (tid == 0) {
        float e = 0.f;
        #pragma unroll
        for (int k = 0; k < PWARP; k++) e += s_eblk[k];
        atomicAdd(out, 0.5f * e);
        if (blockIdx.x == 0) g_buf = buf ^ 1;      // parity for next launch
    }
}

extern "C" void kernel_launch(void* const* d_in, const int* in_sizes, int n_in,
                              void* d_out, int out_size)
{
    const float* pos     = (const float*)d_in[0];
    const float* cell    = (const float*)d_in[1];
    const float* sigm    = (const float*)d_in[2];
    const float* epsm    = (const float*)d_in[3];
    const float* alpm    = (const float*)d_in[4];
    const int*   species = (const int*)  d_in[5];
    const int n = in_sizes[5];
    float* out = (float*)d_out;

    bin_kernel<<<BINBLK, BINTHR>>>(pos, cell, species, out, n);
    pairs_kernel<<<PBLK, PTHR>>>(cell, sigm, epsm, alpm, out, n);
}